// round 2
// baseline (speedup 1.0000x reference)
#include <cuda_runtime.h>
#include <math.h>
#include <math_constants.h>

// Problem constants (fixed by setup_inputs)
#define BQ 2
#define LQ 256
#define HQ 256
#define CQ 5
#define VOCAB 255      // 2*127+1 distinct clipped distances
#define D4H 1024       // 4*H

// Scratch (device globals — no allocations allowed)
__device__ __align__(16) float g_T[VOCAB * HQ];        // rel table @ Wh_w  [255,256]
__device__ __align__(16) float g_A[BQ * LQ * HQ];      // hs@(We+Wd) + Wh_b [B,L,H]
__device__ __align__(16) float g_Bv[BQ * LQ * HQ];     // hs@(Ws-Wd)        [B,L,H]

// ---------------------------------------------------------------------------
// Kernel 1: T[p,h] = sum_i table[p,i] * Wh_w[i,h]   (255 blocks x 256 thr)
// table matches numpy: div = f32(pow(1e4, (2*(i//2))/1024 in f64)); ang = p/div (f32);
// even i -> sin, odd i -> cos.
// ---------------------------------------------------------------------------
__global__ void k_table(const float* __restrict__ Wh_w) {
    __shared__ float row[D4H];
    const int p = blockIdx.x;
    const int t = threadIdx.x;
    for (int i = t; i < D4H; i += 256) {
        double e = (double)(2 * (i >> 1)) / (double)D4H;
        float df = (float)pow(10000.0, e);
        float ang = (float)p / df;
        row[i] = (i & 1) ? cosf(ang) : sinf(ang);
    }
    __syncthreads();
    float acc = 0.f;
    #pragma unroll 4
    for (int i = 0; i < D4H; ++i)
        acc = fmaf(row[i], Wh_w[i * HQ + t], acc);
    g_T[p * HQ + t] = acc;
}

// ---------------------------------------------------------------------------
// Kernel 2: A = hs@(We+Wd)+Wh_b, Bv = hs@(Ws-Wd).   64 blocks x 256 thr,
// each block does 8 rows of hs; thread t owns output column h=t.
// ---------------------------------------------------------------------------
__global__ void k_ab(const float* __restrict__ hs,
                     const float* __restrict__ Wh_w,
                     const float* __restrict__ Wh_b) {
    __shared__ float s_hs[8][HQ];
    const int blk = blockIdx.x;      // 0..63
    const int b = blk >> 5;
    const int i0 = (blk & 31) * 8;
    const int t = threadIdx.x;
    #pragma unroll
    for (int n = 0; n < 8; ++n) {
        int idx = t + n * 256;
        int r = idx >> 8, c = idx & 255;
        s_hs[r][c] = hs[(b * LQ + i0 + r) * HQ + c];
    }
    __syncthreads();
    float accA[8] = {0,0,0,0,0,0,0,0};
    float accB[8] = {0,0,0,0,0,0,0,0};
    const int h = t;
    #pragma unroll 2
    for (int k = 0; k < HQ; ++k) {
        float we = Wh_w[k * HQ + h];
        float ws = Wh_w[(HQ + k) * HQ + h];
        float wd = Wh_w[(2 * HQ + k) * HQ + h];
        float wa = we + wd, wb = ws - wd;
        #pragma unroll
        for (int r = 0; r < 8; ++r) {
            float x = s_hs[r][k];
            accA[r] = fmaf(x, wa, accA[r]);
            accB[r] = fmaf(x, wb, accB[r]);
        }
    }
    float bias = Wh_b[h];
    #pragma unroll
    for (int r = 0; r < 8; ++r) {
        g_A[(b * LQ + i0 + r) * HQ + h]  = accA[r] + bias;
        g_Bv[(b * LQ + i0 + r) * HQ + h] = accB[r];
    }
}

// ---------------------------------------------------------------------------
// Kernel 3 (main, fused): per block: 8 i x 8 j pairs, all H=256, K=256.
// q = (hs_i * hs_j) @ Wm; pre = q + A_i + Bv_j + T[dist]; tanh; @Wo; mask/tril.
// block (32,8): tx = h-group (2 float4 halves), ty = i row. warp == one i.
// ---------------------------------------------------------------------------
__global__ void __launch_bounds__(256, 2)
k_main(const float* __restrict__ hs,
       const int*   __restrict__ mask,
       const float* __restrict__ Wh_w,
       const float* __restrict__ Wo_w,
       const float* __restrict__ Wo_b,
       float* __restrict__ out) {
    __shared__ float sWm[32][HQ];       // 32 KB  Wm K-chunk
    __shared__ float sI[8][32];         // hs rows for i-tile (this chunk)
    __shared__ float sJt[32][8];        // hs rows for j-tile, transposed [k][jl]
    __shared__ float sWo[HQ * CQ];      // 5 KB  output weights

    const int tx = threadIdx.x;         // 0..31
    const int ty = threadIdx.y;         // 0..7
    const int t  = ty * 32 + tx;
    const int b  = blockIdx.z;
    const int i0 = blockIdx.y * 8;
    const int j0 = blockIdx.x * 8;

    for (int idx = t; idx < HQ * CQ; idx += 256) sWo[idx] = Wo_w[idx];

    float acc[8][8];
    #pragma unroll
    for (int p = 0; p < 8; ++p)
        #pragma unroll
        for (int hh = 0; hh < 8; ++hh) acc[p][hh] = 0.f;

    const float* Wm = Wh_w + 3 * HQ * HQ;   // rows [768,1024)

    for (int kc = 0; kc < HQ; kc += 32) {
        __syncthreads();   // protect previous chunk's smem reads (and sWo 1st iter)
        #pragma unroll
        for (int n = 0; n < 8; ++n) {
            int flat = (t + n * 256) * 4;        // float index, 0..8191
            int r = flat >> 8, c = flat & 255;
            *(float4*)&sWm[r][c] = *(const float4*)&Wm[(kc + r) * HQ + c];
        }
        {
            int r = t >> 5, kk = t & 31;
            sI[r][kk]  = hs[(b * LQ + i0 + r) * HQ + kc + kk];
            sJt[kk][r] = hs[(b * LQ + j0 + r) * HQ + kc + kk];
        }
        __syncthreads();
        #pragma unroll 8
        for (int k = 0; k < 32; ++k) {
            float  xI  = sI[ty][k];
            float4 jv0 = *(float4*)&sJt[k][0];
            float4 jv1 = *(float4*)&sJt[k][4];
            float4 w0  = *(float4*)&sWm[k][tx * 4];
            float4 w1  = *(float4*)&sWm[k][128 + tx * 4];
            float xj[8] = { jv0.x * xI, jv0.y * xI, jv0.z * xI, jv0.w * xI,
                            jv1.x * xI, jv1.y * xI, jv1.z * xI, jv1.w * xI };
            #pragma unroll
            for (int p = 0; p < 8; ++p) {
                acc[p][0] = fmaf(xj[p], w0.x, acc[p][0]);
                acc[p][1] = fmaf(xj[p], w0.y, acc[p][1]);
                acc[p][2] = fmaf(xj[p], w0.z, acc[p][2]);
                acc[p][3] = fmaf(xj[p], w0.w, acc[p][3]);
                acc[p][4] = fmaf(xj[p], w1.x, acc[p][4]);
                acc[p][5] = fmaf(xj[p], w1.y, acc[p][5]);
                acc[p][6] = fmaf(xj[p], w1.z, acc[p][6]);
                acc[p][7] = fmaf(xj[p], w1.w, acc[p][7]);
            }
        }
    }

    // ---------------- epilogue ----------------
    const int i_g = i0 + ty;
    const int mi  = mask[b * LQ + i_g];

    float aval[8];
    {
        const float* Arow = &g_A[(b * LQ + i_g) * HQ];
        float4 a0 = *(const float4*)&Arow[tx * 4];
        float4 a1 = *(const float4*)&Arow[128 + tx * 4];
        aval[0]=a0.x; aval[1]=a0.y; aval[2]=a0.z; aval[3]=a0.w;
        aval[4]=a1.x; aval[5]=a1.y; aval[6]=a1.z; aval[7]=a1.w;
    }

    #pragma unroll 1
    for (int jl = 0; jl < 8; ++jl) {
        const int j_g = j0 + jl;
        float bval[8], tval[8];
        {
            const float* Brow = &g_Bv[(b * LQ + j_g) * HQ];
            float4 b0 = *(const float4*)&Brow[tx * 4];
            float4 b1 = *(const float4*)&Brow[128 + tx * 4];
            bval[0]=b0.x; bval[1]=b0.y; bval[2]=b0.z; bval[3]=b0.w;
            bval[4]=b1.x; bval[5]=b1.y; bval[6]=b1.z; bval[7]=b1.w;
            int d = j_g - i_g;
            d = (d > 127 ? 127 : (d < -127 ? -127 : d)) + 127;
            const float* Trow = &g_T[d * HQ];
            float4 t0 = *(const float4*)&Trow[tx * 4];
            float4 t1 = *(const float4*)&Trow[128 + tx * 4];
            tval[0]=t0.x; tval[1]=t0.y; tval[2]=t0.z; tval[3]=t0.w;
            tval[4]=t1.x; tval[5]=t1.y; tval[6]=t1.z; tval[7]=t1.w;
        }
        float part[5] = {0,0,0,0,0};
        #pragma unroll
        for (int hh = 0; hh < 8; ++hh) {
            int h = (hh < 4) ? (tx * 4 + hh) : (128 + tx * 4 + hh - 4);
            float pre = acc[jl][hh] + aval[hh] + bval[hh] + tval[hh];
            float tv  = tanhf(pre);
            const float* wr = &sWo[h * CQ];
            part[0] = fmaf(tv, wr[0], part[0]);
            part[1] = fmaf(tv, wr[1], part[1]);
            part[2] = fmaf(tv, wr[2], part[2]);
            part[3] = fmaf(tv, wr[3], part[3]);
            part[4] = fmaf(tv, wr[4], part[4]);
        }
        #pragma unroll
        for (int c = 0; c < 5; ++c) {
            float v = part[c];
            #pragma unroll
            for (int off = 16; off; off >>= 1)
                v += __shfl_xor_sync(0xffffffffu, v, off);
            part[c] = v;
        }
        if (tx == 0) {
            const int mj = mask[b * LQ + j_g];
            const bool bad = (mi == 0) || (mj == 0);
            #pragma unroll
            for (int c = 0; c < 5; ++c) {
                float v = part[c] + Wo_b[c];
                if (bad)                v = -CUDART_INF_F;
                else if (i_g > j_g)     v -= 1e12f;
                out[((b * CQ + c) * LQ + i_g) * LQ + j_g] = v;
            }
        }
    }
}

// ---------------------------------------------------------------------------
extern "C" void kernel_launch(void* const* d_in, const int* in_sizes, int n_in,
                              void* d_out, int out_size) {
    // Robust remap by element count (all six sizes are distinct):
    const float* hs   = nullptr;   // 131072
    const int*   mask = nullptr;   // 512
    const float* Wh_w = nullptr;   // 262144
    const float* Wh_b = nullptr;   // 256
    const float* Wo_w = nullptr;   // 1280
    const float* Wo_b = nullptr;   // 5
    for (int i = 0; i < n_in; ++i) {
        switch (in_sizes[i]) {
            case 131072: hs   = (const float*)d_in[i]; break;
            case 512:    mask = (const int*)  d_in[i]; break;
            case 262144: Wh_w = (const float*)d_in[i]; break;
            case 256:    Wh_b = (const float*)d_in[i]; break;
            case 1280:   Wo_w = (const float*)d_in[i]; break;
            case 5:      Wo_b = (const float*)d_in[i]; break;
        }
    }
    float* out = (float*)d_out;

    k_table<<<VOCAB, 256>>>(Wh_w);
    k_ab<<<64, 256>>>(hs, Wh_w, Wh_b);
    dim3 grid(LQ / 8, LQ / 8, BQ);
    dim3 blk(32, 8);
    k_main<<<grid, blk>>>(hs, mask, Wh_w, Wo_w, Wo_b, out);
}

// round 6
// speedup vs baseline: 3.5402x; 3.5402x over previous
#include <cuda_runtime.h>
#include <cuda_bf16.h>
#include <math.h>
#include <math_constants.h>
#include <stdint.h>

// Problem constants (fixed by setup_inputs)
#define BQ 2
#define LQ 256
#define HQ 256
#define CQ 5
#define VOCAB 255      // 2*127+1 distinct clipped distances
#define D4H 1024       // 4*H

// Scratch (device globals — no allocations allowed)
__device__ __align__(16) float g_T[VOCAB * HQ];          // sin-table @ Wh_w [255,256]
__device__ __align__(16) float g_A[BQ * LQ * HQ];        // hs@(We+Wd)+b    [B,L,H]
__device__ __align__(16) float g_Bv[BQ * LQ * HQ];       // hs@(Ws-Wd)      [B,L,H]
__device__ __align__(16) __nv_bfloat16 g_WmT[HQ * HQ];   // Wm^T bf16 [h][k]

// ---------------------------------------------------------------------------
// helpers
// ---------------------------------------------------------------------------
__device__ __forceinline__ uint32_t smem_u32(const void* p) {
    uint32_t a;
    asm("{ .reg .u64 t; cvta.to.shared.u64 t, %1; cvt.u32.u64 %0, t; }"
        : "=r"(a) : "l"(p));
    return a;
}
__device__ __forceinline__ float tanhfast(float x) {
    float r;
    asm("tanh.approx.f32 %0, %1;" : "=f"(r) : "f"(x));
    return r;
}
#define LDSM4(R0, R1, R2, R3, ADDR) \
    asm volatile("ldmatrix.sync.aligned.m8n8.x4.shared.b16 {%0,%1,%2,%3}, [%4];" \
                 : "=r"(R0), "=r"(R1), "=r"(R2), "=r"(R3) : "r"(ADDR))
#define MMA16816(D, A, B) \
    asm volatile("mma.sync.aligned.m16n8k16.row.col.f32.bf16.bf16.f32 " \
                 "{%0,%1,%2,%3},{%4,%5,%6,%7},{%8,%9},{%0,%1,%2,%3};" \
                 : "+f"((D)[0]), "+f"((D)[1]), "+f"((D)[2]), "+f"((D)[3]) \
                 : "r"((A)[0]), "r"((A)[1]), "r"((A)[2]), "r"((A)[3]), \
                   "r"((B)[0]), "r"((B)[1]))

// ---------------------------------------------------------------------------
// Kernel: T[p,:] = sinusoid_row(p) @ Wh_w.   255 blocks x 256 thr.
// Sinusoid matches numpy: div = 10000^((2*(i//2))/1024); even->sin, odd->cos.
// ---------------------------------------------------------------------------
__global__ void k_tgemm(const float* __restrict__ Wh_w) {
    __shared__ float s[D4H];
    const int p = blockIdx.x;
    const int t = threadIdx.x;
    const float fp = (float)p;
    for (int i = t; i < D4H; i += 256) {
        float e = (float)(2 * (i >> 1)) * (13.287712379549449f / 1024.f); // log2(1e4)*x/1024
        float ang = fp * exp2f(-e);
        s[i] = (i & 1) ? cosf(ang) : sinf(ang);
    }
    __syncthreads();
    float a0 = 0.f, a1 = 0.f, a2 = 0.f, a3 = 0.f;
    #pragma unroll 8
    for (int k = 0; k < 256; ++k) {
        a0 = fmaf(s[k],       Wh_w[(k)       * HQ + t], a0);
        a1 = fmaf(s[k + 256], Wh_w[(k + 256) * HQ + t], a1);
        a2 = fmaf(s[k + 512], Wh_w[(k + 512) * HQ + t], a2);
        a3 = fmaf(s[k + 768], Wh_w[(k + 768) * HQ + t], a3);
    }
    g_T[p * HQ + t] = (a0 + a1) + (a2 + a3);
}

// ---------------------------------------------------------------------------
// Kernel: A = hs@(We+Wd)+Wh_b, Bv = hs@(Ws-Wd)
// ---------------------------------------------------------------------------
__global__ void k_ab(const float* __restrict__ hs,
                     const float* __restrict__ Wh_w,
                     const float* __restrict__ Wh_b) {
    __shared__ float s_hs[8][HQ];
    const int blk = blockIdx.x;
    const int b = blk >> 5;
    const int i0 = (blk & 31) * 8;
    const int t = threadIdx.x;
    #pragma unroll
    for (int n = 0; n < 8; ++n) {
        int idx = t + n * 256;
        s_hs[idx >> 8][idx & 255] = hs[(b * LQ + i0 + (idx >> 8)) * HQ + (idx & 255)];
    }
    __syncthreads();
    float accA[8] = {0,0,0,0,0,0,0,0};
    float accB[8] = {0,0,0,0,0,0,0,0};
    const int h = t;
    #pragma unroll 4
    for (int k = 0; k < HQ; ++k) {
        float we = Wh_w[k * HQ + h];
        float ws = Wh_w[(HQ + k) * HQ + h];
        float wd = Wh_w[(2 * HQ + k) * HQ + h];
        float wa = we + wd, wb = ws - wd;
        #pragma unroll
        for (int r = 0; r < 8; ++r) {
            float x = s_hs[r][k];
            accA[r] = fmaf(x, wa, accA[r]);
            accB[r] = fmaf(x, wb, accB[r]);
        }
    }
    float bias = Wh_b[h];
    #pragma unroll
    for (int r = 0; r < 8; ++r) {
        g_A[(b * LQ + i0 + r) * HQ + h]  = accA[r] + bias;
        g_Bv[(b * LQ + i0 + r) * HQ + h] = accB[r];
    }
}

// ---------------------------------------------------------------------------
// Kernel: WmT[h][k] = bf16(Wm[k][h]),  Wm = Wh_w rows [768,1024)
// ---------------------------------------------------------------------------
__global__ void k_trans(const float* __restrict__ Wh_w) {
    __shared__ float tile[32][33];
    const int k0 = blockIdx.x * 32, h0 = blockIdx.y * 32;
    const int tx = threadIdx.x, ty = threadIdx.y;
    tile[ty][tx] = Wh_w[(3 * HQ + k0 + ty) * HQ + h0 + tx];
    __syncthreads();
    g_WmT[(h0 + ty) * HQ + k0 + tx] = __float2bfloat16(tile[tx][ty]);
}

// ---------------------------------------------------------------------------
// Main fused kernel (warp-level mma.sync bf16, compute_103-safe):
// block (b, i, j-tile of 128): D[j,h] = sum_k (hs_j[k]*hs_i[k]) * Wm[k,h]
// 512 threads = 16 warps in 4(j) x 4(h); warp tile 32j x 64h.
// Epilogue: pre = D + A_i + Bv_j + T[clip(j-i)]; tanh; @Wo; reduce; mask; write.
// ---------------------------------------------------------------------------
#define RS 40   // smem row stride in bf16 (80 bytes) -> conflict-free ldmatrix

__global__ void __launch_bounds__(512, 1)
k_main(const float* __restrict__ hs,
       const int*   __restrict__ mask,
       const float* __restrict__ Wo_w,
       const float* __restrict__ Wo_b,
       float* __restrict__ out) {
    __shared__ __align__(16) __nv_bfloat16 sA[128 * RS];  // 10 KB product tile
    __shared__ __align__(16) __nv_bfloat16 sB[256 * RS];  // 20 KB WmT tile
    __shared__ float sHi[HQ];
    __shared__ float sAi[HQ];
    __shared__ float sWoT[CQ][HQ];
    __shared__ float sPart[CQ][128];

    const int t = threadIdx.x;
    const int lane = t & 31, w = t >> 5;
    const int warp_j = w >> 2, warp_h = w & 3;
    const int j0 = blockIdx.x * 128;
    const int i_g = blockIdx.y;
    const int b = blockIdx.z;

    // ---- prefill ----
    if (t < HQ) {
        sHi[t] = hs[(b * LQ + i_g) * HQ + t];
        sAi[t] = g_A[(b * LQ + i_g) * HQ + t];
    }
    for (int idx = t; idx < HQ * CQ; idx += 512) {
        int h = idx / CQ, c = idx % CQ;
        sWoT[c][h] = Wo_w[idx];
    }
    for (int idx = t; idx < CQ * 128; idx += 512)
        sPart[idx >> 7][idx & 127] = 0.f;

    const uint32_t sAb = smem_u32(sA);
    const uint32_t sBb = smem_u32(sB);

    float acc[2][8][4];
    #pragma unroll
    for (int jt = 0; jt < 2; ++jt)
        #pragma unroll
        for (int ht = 0; ht < 8; ++ht)
            #pragma unroll
            for (int u = 0; u < 4; ++u) acc[jt][ht][u] = 0.f;

    const int jrow_f = t >> 2;            // fill: row 0..127
    const int k0_f   = (t & 3) * 8;       // fill: k-group

    #pragma unroll 1
    for (int c = 0; c < 8; ++c) {
        const int kc = c * 32;
        __syncthreads();   // prev chunk consumed (and prefill on first iter)

        // A tile: [128 j x 32 k] bf16 = hs_j * hs_i
        {
            const float4* src =
                (const float4*)(hs + (b * LQ + j0 + jrow_f) * HQ + kc + k0_f);
            float4 lo = src[0], hi = src[1];
            const float* hv = &sHi[kc + k0_f];
            __nv_bfloat162 p0 = __floats2bfloat162_rn(lo.x * hv[0], lo.y * hv[1]);
            __nv_bfloat162 p1 = __floats2bfloat162_rn(lo.z * hv[2], lo.w * hv[3]);
            __nv_bfloat162 p2 = __floats2bfloat162_rn(hi.x * hv[4], hi.y * hv[5]);
            __nv_bfloat162 p3 = __floats2bfloat162_rn(hi.z * hv[6], hi.w * hv[7]);
            uint4 v;
            v.x = *(uint32_t*)&p0; v.y = *(uint32_t*)&p1;
            v.z = *(uint32_t*)&p2; v.w = *(uint32_t*)&p3;
            *(uint4*)((char*)sA + jrow_f * (RS * 2) + k0_f * 2) = v;
        }
        // B tile: [256 h x 32 k] bf16 from g_WmT
        #pragma unroll
        for (int it = 0; it < 2; ++it) {
            int idx = it * 512 + t;
            int row = idx >> 2, kg = (idx & 3) * 8;
            uint4 v = *(const uint4*)(g_WmT + row * HQ + kc + kg);
            *(uint4*)((char*)sB + row * (RS * 2) + kg * 2) = v;
        }
        __syncthreads();

        // ---- MMA: 2 k-steps of 16 ----
        #pragma unroll
        for (int kk = 0; kk < 32; kk += 16) {
            uint32_t aF[2][4];
            #pragma unroll
            for (int jt = 0; jt < 2; ++jt) {
                int row = warp_j * 32 + jt * 16 + (lane & 15);
                int ko = kk + ((lane >> 4) << 3);
                LDSM4(aF[jt][0], aF[jt][1], aF[jt][2], aF[jt][3],
                      sAb + row * (RS * 2) + ko * 2);
            }
            uint32_t bF[8][2];
            #pragma unroll
            for (int p = 0; p < 4; ++p) {
                int row = warp_h * 64 + p * 16 + (lane & 7) + ((lane >> 4) << 3);
                int ko = kk + (((lane >> 3) & 1) << 3);
                LDSM4(bF[2 * p][0], bF[2 * p][1], bF[2 * p + 1][0], bF[2 * p + 1][1],
                      sBb + row * (RS * 2) + ko * 2);
            }
            #pragma unroll
            for (int jt = 0; jt < 2; ++jt)
                #pragma unroll
                for (int ht = 0; ht < 8; ++ht)
                    MMA16816(acc[jt][ht], aF[jt], bF[ht]);
        }
    }

    // ---- epilogue ----
    const int g  = lane >> 2;
    const int c2 = (lane & 3) << 1;

    #pragma unroll
    for (int jt = 0; jt < 2; ++jt) {
        #pragma unroll
        for (int rr = 0; rr < 2; ++rr) {
            const int j_loc = warp_j * 32 + jt * 16 + rr * 8 + g;
            const int j_g = j0 + j_loc;
            int d = j_g - i_g;
            d = (d > 127 ? 127 : (d < -127 ? -127 : d)) + 127;
            const float* rB = g_Bv + (b * LQ + j_g) * HQ;
            const float* rT = g_T + d * HQ;
            float part[5] = {0.f, 0.f, 0.f, 0.f, 0.f};
            #pragma unroll
            for (int ht = 0; ht < 8; ++ht) {
                const int h = warp_h * 64 + ht * 8 + c2;
                float dv0 = acc[jt][ht][rr * 2 + 0];
                float dv1 = acc[jt][ht][rr * 2 + 1];
                float2 bv = *(const float2*)(rB + h);
                float2 tv = *(const float2*)(rT + h);
                float th0 = tanhfast(dv0 + sAi[h]     + bv.x + tv.x);
                float th1 = tanhfast(dv1 + sAi[h + 1] + bv.y + tv.y);
                #pragma unroll
                for (int cc = 0; cc < 5; ++cc) {
                    float2 wv = *(const float2*)&sWoT[cc][h];
                    part[cc] = fmaf(th0, wv.x, fmaf(th1, wv.y, part[cc]));
                }
            }
            #pragma unroll
            for (int cc = 0; cc < 5; ++cc) {
                part[cc] += __shfl_xor_sync(0xffffffffu, part[cc], 1);
                part[cc] += __shfl_xor_sync(0xffffffffu, part[cc], 2);
            }
            if ((lane & 3) == 0) {
                #pragma unroll
                for (int cc = 0; cc < 5; ++cc)
                    atomicAdd(&sPart[cc][j_loc], part[cc]);
            }
        }
    }
    __syncthreads();

    const int mi = mask[b * LQ + i_g];
    for (int idx = t; idx < CQ * 128; idx += 512) {
        const int cc = idx >> 7, jl = idx & 127;
        const int j_g = j0 + jl;
        const int mj = mask[b * LQ + j_g];
        float v = sPart[cc][jl] + Wo_b[cc];
        if (mi == 0 || mj == 0) v = -CUDART_INF_F;
        else if (i_g > j_g)     v -= 1e12f;
        out[((b * CQ + cc) * LQ + i_g) * LQ + j_g] = v;
    }
}

// ---------------------------------------------------------------------------
extern "C" void kernel_launch(void* const* d_in, const int* in_sizes, int n_in,
                              void* d_out, int out_size) {
    const float* hs   = nullptr;   // 131072
    const int*   mask = nullptr;   // 512
    const float* Wh_w = nullptr;   // 262144
    const float* Wh_b = nullptr;   // 256
    const float* Wo_w = nullptr;   // 1280
    const float* Wo_b = nullptr;   // 5
    for (int i = 0; i < n_in; ++i) {
        switch (in_sizes[i]) {
            case 131072: hs   = (const float*)d_in[i]; break;
            case 512:    mask = (const int*)  d_in[i]; break;
            case 262144: Wh_w = (const float*)d_in[i]; break;
            case 256:    Wh_b = (const float*)d_in[i]; break;
            case 1280:   Wo_w = (const float*)d_in[i]; break;
            case 5:      Wo_b = (const float*)d_in[i]; break;
        }
    }
    float* out = (float*)d_out;

    k_tgemm<<<VOCAB, 256>>>(Wh_w);
    k_ab<<<64, 256>>>(hs, Wh_w, Wh_b);
    {
        dim3 g(8, 8); dim3 blk(32, 32);
        k_trans<<<g, blk>>>(Wh_w);
    }
    {
        dim3 grid(LQ / 128, LQ, BQ);     // (2, 256, 2) = 1024 blocks
        k_main<<<grid, 512>>>(hs, mask, Wo_w, Wo_b, out);
    }
}